// round 2
// baseline (speedup 1.0000x reference)
#include <cuda_runtime.h>
#include <math.h>

// ---------------- problem constants ----------------
constexpr int Bb = 4, Ss = 1024, Tt = Bb * Ss;   // 4096 tokens
constexpr int Dd = 768, Hh = 12, DH = 64, NOPE = 32, ROPE = 32;
constexpr int QP = 384, KVP = 512, CKV = 544;    // KVP + ROPE
constexpr int UKVO = Dd + Hh * NOPE;             // 1152
constexpr int Ee = 8, NSs = 2, FF = 3072;

// ---------------- scratch (device globals; no allocation) ----------------
__device__ float g_h   [(size_t)Tt * Dd];
__device__ float g_cq  [(size_t)Tt * QP];
__device__ float g_Q   [(size_t)Tt * Dd];
__device__ float g_ckv [(size_t)Tt * CKV];
__device__ float g_kvl [(size_t)Tt * KVP];
__device__ float g_KV  [(size_t)Tt * UKVO];
__device__ float g_q   [(size_t)Tt * Dd];   // [b][h][s][64]
__device__ float g_k   [(size_t)Tt * Dd];
__device__ float g_v   [(size_t)Tt * Dd];
__device__ float g_o   [(size_t)Tt * Dd];   // [t][h*64+d]
__device__ float g_x2  [(size_t)Tt * Dd];
__device__ float g_h2  [(size_t)Tt * Dd];
__device__ float g_ts  [(size_t)Tt * FF];        // shared-expert intermediate
__device__ float g_t1  [(size_t)2 * Tt * FF];    // routed fc output by slot
__device__ float g_y   [(size_t)2 * Tt * Dd];    // routed proj output by slot
__device__ int   g_cnt [Ee];
__device__ int   g_list[Ee * Tt];
__device__ int   g_slot[Ee * Tt];
__device__ float g_gate[Ee * Tt];

// ---------------- helpers ----------------
__device__ __forceinline__ float gelu_exact(float v) {
    return 0.5f * v * (1.0f + erff(v * 0.70710678118654752f));
}

__device__ __forceinline__ void block_reduce2(float& s, float& s2) {
    __shared__ float sh[16], sh2[16];
    int lane = threadIdx.x & 31, w = threadIdx.x >> 5;
    #pragma unroll
    for (int o = 16; o; o >>= 1) {
        s  += __shfl_xor_sync(0xffffffffu, s,  o);
        s2 += __shfl_xor_sync(0xffffffffu, s2, o);
    }
    if (lane == 0) { sh[w] = s; sh2[w] = s2; }
    __syncthreads();
    int nw = blockDim.x >> 5;
    if (w == 0) {
        float a  = lane < nw ? sh[lane]  : 0.f;
        float a2 = lane < nw ? sh2[lane] : 0.f;
        #pragma unroll
        for (int o = 16; o; o >>= 1) {
            a  += __shfl_xor_sync(0xffffffffu, a,  o);
            a2 += __shfl_xor_sync(0xffffffffu, a2, o);
        }
        if (lane == 0) { sh[0] = a; sh2[0] = a2; }
    }
    __syncthreads();
    s = sh[0]; s2 = sh2[0];
}

// ---------------- layernorm: one block per row ----------------
__global__ void ln_k(const float* __restrict__ x, const float* __restrict__ w,
                     const float* __restrict__ b, float* __restrict__ y,
                     int len, int xs, int ys) {
    int row = blockIdx.x;
    const float* xp = x + (size_t)row * xs;
    float* yp = y + (size_t)row * ys;
    float s = 0.f, s2 = 0.f;
    for (int i = threadIdx.x; i < len; i += blockDim.x) {
        float v = xp[i]; s += v; s2 += v * v;
    }
    block_reduce2(s, s2);
    float mean = s / len;
    float var = fmaxf(s2 / len - mean * mean, 0.f);
    float inv = rsqrtf(var + 1e-5f);
    for (int i = threadIdx.x; i < len; i += blockDim.x) {
        float v = (xp[i] - mean) * inv * w[i];
        if (b) v += b[i];
        yp[i] = v;
    }
}

// ---------------- generic tiled GEMM ----------------
// C[M,N] = A[M,K] * op(B) ; op(B) = B (K x N, TB=false) or B^T (B is N x K, TB=true)
// EPI: 0 store, 1 +R, 2 gelu, 3 *rowscale, 4 accumulate into C
template<bool TB, int EPI>
__global__ __launch_bounds__(256)
void gemm_k(const float* __restrict__ A, const float* __restrict__ Bm,
            const float* __restrict__ R, float* __restrict__ C,
            int M, int N, int K, int lda, int ldb, int ldc,
            const int* __restrict__ gA, const int* __restrict__ gC,
            const float* __restrict__ gs, const int* __restrict__ dM) {
    int Me = M;
    if (dM) Me = *dM;
    int bm = blockIdx.y * 64, bn = blockIdx.x * 64;
    if (bm >= Me) return;

    __shared__ float As[16][64];
    __shared__ float Bs[16][64];
    int tid = threadIdx.x;
    int tx = tid & 15, ty = tid >> 4;
    float acc[4][4] = {};

    int ar = tid >> 2;
    int ak = (tid & 3) * 4;
    int arow = bm + ar;
    int aIdx = -1;
    if (arow < Me) aIdx = gA ? gA[arow] : arow;

    for (int k0 = 0; k0 < K; k0 += 16) {
        // A tile (K assumed multiple of 16)
        #pragma unroll
        for (int i = 0; i < 4; i++) {
            float v = 0.f;
            if (aIdx >= 0) v = A[(size_t)aIdx * lda + k0 + ak + i];
            As[ak + i][ar] = v;
        }
        if (!TB) {
            int kr = tid >> 4, c = (tid & 15) * 4;
            #pragma unroll
            for (int i = 0; i < 4; i++) {
                int col = bn + c + i;
                Bs[kr][c + i] = (col < N) ? Bm[(size_t)(k0 + kr) * ldb + col] : 0.f;
            }
        } else {
            int br = tid >> 2, bk = (tid & 3) * 4;
            int col = bn + br;
            #pragma unroll
            for (int i = 0; i < 4; i++) {
                Bs[bk + i][br] = (col < N) ? Bm[(size_t)col * ldb + k0 + bk + i] : 0.f;
            }
        }
        __syncthreads();
        #pragma unroll
        for (int kk = 0; kk < 16; kk++) {
            float a[4], b[4];
            #pragma unroll
            for (int i = 0; i < 4; i++) a[i] = As[kk][ty * 4 + i];
            #pragma unroll
            for (int j = 0; j < 4; j++) b[j] = Bs[kk][tx * 4 + j];
            #pragma unroll
            for (int i = 0; i < 4; i++)
                #pragma unroll
                for (int j = 0; j < 4; j++)
                    acc[i][j] += a[i] * b[j];
        }
        __syncthreads();
    }

    #pragma unroll
    for (int i = 0; i < 4; i++) {
        int r = bm + ty * 4 + i;
        if (r >= Me) continue;
        int cr = gC ? gC[r] : r;
        float rs = (EPI == 3) ? gs[r] : 1.f;
        #pragma unroll
        for (int j = 0; j < 4; j++) {
            int col = bn + tx * 4 + j;
            if (col >= N) continue;
            float v = acc[i][j];
            if (EPI == 1) v += R[(size_t)cr * ldc + col];
            if (EPI == 2) v = gelu_exact(v);
            if (EPI == 3) v *= rs;
            float* cp = &C[(size_t)cr * ldc + col];
            if (EPI == 4) *cp = *cp + v;
            else          *cp = v;
        }
    }
}

template<bool TB, int EPI>
static void launch_gemm(const float* A, const float* B, const float* R, float* C,
                        int M, int N, int K, int lda, int ldb, int ldc,
                        const int* gA, const int* gC, const float* gs, const int* dM) {
    dim3 grid((N + 63) / 64, (M + 63) / 64);
    gemm_k<TB, EPI><<<grid, 256>>>(A, B, R, C, M, N, K, lda, ldb, ldc, gA, gC, gs, dM);
}

// ---------------- RoPE + per-head q/k/v layout ----------------
__global__ void build_qkv_k(const float* __restrict__ Q, const float* __restrict__ KV,
                            const float* __restrict__ ckv,
                            float* __restrict__ q, float* __restrict__ k,
                            float* __restrict__ v) {
    int t = blockIdx.x;
    int h = blockIdx.y;
    int d = threadIdx.x;          // 0..63
    int b = t / Ss, s = t - b * Ss;
    const float ln1e4_32 = 0.28782313662425574f;  // ln(10000)/32

    size_t dst = ((size_t)(b * Hh + h) * Ss + s) * 64 + d;

    float qv, kv;
    if (d < NOPE) {
        qv = Q [(size_t)t * Dd   + h * DH + d];
        kv = KV[(size_t)t * UKVO + h * (NOPE + DH) + d];
    } else {
        int j = d - NOPE;            // 0..31
        int j16 = j & 15;
        float freq = expf(-ln1e4_32 * (float)j16);
        float ang = (float)s * freq;
        float cs = cosf(ang), sn = sinf(ang);
        // q rope
        {
            float xv = Q[(size_t)t * Dd + h * DH + NOPE + j];
            float pr = (j < 16) ? Q[(size_t)t * Dd + h * DH + NOPE + j + 16]
                                : Q[(size_t)t * Dd + h * DH + NOPE + j - 16];
            qv = (j < 16) ? xv * cs - pr * sn : xv * cs + pr * sn;
        }
        // k rope (shared across heads)
        {
            float xv = ckv[(size_t)t * CKV + KVP + j];
            float pr = (j < 16) ? ckv[(size_t)t * CKV + KVP + j + 16]
                                : ckv[(size_t)t * CKV + KVP + j - 16];
            kv = (j < 16) ? xv * cs - pr * sn : xv * cs + pr * sn;
        }
    }
    q[dst] = qv * 0.125f;   // 1/sqrt(64) folded into q
    k[dst] = kv;
    v[dst] = KV[(size_t)t * UKVO + h * (NOPE + DH) + NOPE + d];
}

// ---------------- causal flash attention: 1 thread = 1 query row ----------------
__global__ __launch_bounds__(128)
void attn_k(const float* __restrict__ q, const float* __restrict__ k,
            const float* __restrict__ v, float* __restrict__ o) {
    int bh = blockIdx.y;                // 0..B*H-1
    int qi = blockIdx.x * 128 + threadIdx.x;
    const float* qp = q + ((size_t)bh * Ss + qi) * 64;

    float qr[64];
    #pragma unroll
    for (int d = 0; d < 64; d++) qr[d] = qp[d];

    float acc[64];
    #pragma unroll
    for (int d = 0; d < 64; d++) acc[d] = 0.f;
    float m = -1e30f, l = 0.f;

    __shared__ float Ks[64][64];
    __shared__ float Vs[64][64];

    int ktmax = (blockIdx.x * 128 + 127) >> 6;
    for (int kt = 0; kt <= ktmax; kt++) {
        // cooperative tile load: 64 rows x 16 float4
        for (int i = threadIdx.x; i < 64 * 16; i += 128) {
            int row = i >> 4, c = i & 15;
            size_t base = ((size_t)bh * Ss + kt * 64 + row) * 64;
            ((float4*)&Ks[row][0])[c] = ((const float4*)(k + base))[c];
            ((float4*)&Vs[row][0])[c] = ((const float4*)(v + base))[c];
        }
        __syncthreads();
        int kbase = kt * 64;
        for (int kk = 0; kk < 64; kk++) {
            int key = kbase + kk;
            if (key > qi) break;
            float sc = 0.f;
            #pragma unroll
            for (int d = 0; d < 64; d++) sc += qr[d] * Ks[kk][d];
            float nm = fmaxf(m, sc);
            float corr = __expf(m - nm);
            float p = __expf(sc - nm);
            l = l * corr + p;
            #pragma unroll
            for (int d = 0; d < 64; d++) acc[d] = acc[d] * corr + p * Vs[kk][d];
            m = nm;
        }
        __syncthreads();
    }
    int b = bh / Hh, h = bh - b * Hh;
    float invl = 1.f / l;
    float* op = o + ((size_t)(b * Ss + qi)) * Dd + h * DH;
    #pragma unroll
    for (int d = 0; d < 64; d++) op[d] = acc[d] * invl;
}

// ---------------- MoE routing: one warp per token ----------------
__global__ void route_k(const float* __restrict__ h2, const float* __restrict__ cent,
                        const float* __restrict__ rb, int* __restrict__ cnt,
                        int* __restrict__ list, int* __restrict__ slot,
                        float* __restrict__ gate) {
    int gw = (blockIdx.x * blockDim.x + threadIdx.x) >> 5;
    int lane = threadIdx.x & 31;
    if (gw >= Tt) return;
    const float* hp = h2 + (size_t)gw * Dd;
    float raw[Ee];
    #pragma unroll
    for (int e = 0; e < Ee; e++) {
        float s = 0.f;
        const float* cp = cent + (size_t)e * Dd;
        for (int d = lane; d < Dd; d += 32) s += hp[d] * cp[d];
        #pragma unroll
        for (int o = 16; o; o >>= 1) s += __shfl_xor_sync(0xffffffffu, s, o);
        raw[e] = s;
    }
    if (lane == 0) {
        int e1 = 0; float b1 = -1e30f;
        #pragma unroll
        for (int e = 0; e < Ee; e++) {
            float bv = raw[e] + rb[e];
            if (bv > b1) { b1 = bv; e1 = e; }
        }
        int e2 = -1; float b2 = -1e30f;
        #pragma unroll
        for (int e = 0; e < Ee; e++) {
            if (e == e1) continue;
            float bv = raw[e] + rb[e];
            if (bv > b2) { b2 = bv; e2 = e; }
        }
        float w1 = 1.f / (1.f + expf(-raw[e1]));
        float w2 = 1.f / (1.f + expf(-raw[e2]));
        float inv = 1.f / (w1 + w2 + 1e-9f);
        w1 *= inv; w2 *= inv;
        int p1 = atomicAdd(&cnt[e1], 1);
        list[e1 * Tt + p1] = gw; slot[e1 * Tt + p1] = 2 * gw;     gate[e1 * Tt + p1] = w1;
        int p2 = atomicAdd(&cnt[e2], 1);
        list[e2 * Tt + p2] = gw; slot[e2 * Tt + p2] = 2 * gw + 1; gate[e2 * Tt + p2] = w2;
    }
}

// ---------------- small utility kernels ----------------
__global__ void reset_k(int* cnt) {
    if (threadIdx.x < Ee) cnt[threadIdx.x] = 0;
}
__global__ void copy4_k(float* __restrict__ dst, const float* __restrict__ src, int n4) {
    int i = blockIdx.x * blockDim.x + threadIdx.x;
    if (i < n4) ((float4*)dst)[i] = ((const float4*)src)[i];
}
__global__ void addroute_k(float* __restrict__ out, const float* __restrict__ y) {
    int i = blockIdx.x * blockDim.x + threadIdx.x;
    if (i < Tt * Dd) {
        int t = i / Dd, d = i - t * Dd;
        out[i] += y[(size_t)(2 * t) * Dd + d] + y[(size_t)(2 * t + 1) * Dd + d];
    }
}

// ---------------- launch sequence ----------------
extern "C" void kernel_launch(void* const* d_in, const int* in_sizes, int n_in,
                              void* d_out, int out_size) {
    const float* x        = (const float*)d_in[0];
    const float* ln1_w    = (const float*)d_in[1];
    const float* ln2_w    = (const float*)d_in[2];
    const float* W_dq     = (const float*)d_in[3];
    const float* W_uq     = (const float*)d_in[4];
    const float* q_ln_w   = (const float*)d_in[5];
    const float* q_ln_b   = (const float*)d_in[6];
    const float* W_dkv    = (const float*)d_in[7];
    const float* W_ukv    = (const float*)d_in[8];
    const float* kv_ln_w  = (const float*)d_in[9];
    const float* kv_ln_b  = (const float*)d_in[10];
    const float* W_o      = (const float*)d_in[11];
    const float* s_fc     = (const float*)d_in[12];
    const float* s_proj   = (const float*)d_in[13];
    const float* e_fc     = (const float*)d_in[14];
    const float* e_proj   = (const float*)d_in[15];
    const float* cent     = (const float*)d_in[16];
    const float* rbias    = (const float*)d_in[17];
    float* out = (float*)d_out;

    float *h, *cq, *Q, *ckv, *kvl, *KV, *q, *k, *v, *o, *x2, *h2, *ts, *t1, *y, *gate;
    int *cnt, *list, *slot;
    cudaGetSymbolAddress((void**)&h,    g_h);
    cudaGetSymbolAddress((void**)&cq,   g_cq);
    cudaGetSymbolAddress((void**)&Q,    g_Q);
    cudaGetSymbolAddress((void**)&ckv,  g_ckv);
    cudaGetSymbolAddress((void**)&kvl,  g_kvl);
    cudaGetSymbolAddress((void**)&KV,   g_KV);
    cudaGetSymbolAddress((void**)&q,    g_q);
    cudaGetSymbolAddress((void**)&k,    g_k);
    cudaGetSymbolAddress((void**)&v,    g_v);
    cudaGetSymbolAddress((void**)&o,    g_o);
    cudaGetSymbolAddress((void**)&x2,   g_x2);
    cudaGetSymbolAddress((void**)&h2,   g_h2);
    cudaGetSymbolAddress((void**)&ts,   g_ts);
    cudaGetSymbolAddress((void**)&t1,   g_t1);
    cudaGetSymbolAddress((void**)&y,    g_y);
    cudaGetSymbolAddress((void**)&gate, g_gate);
    cudaGetSymbolAddress((void**)&cnt,  g_cnt);
    cudaGetSymbolAddress((void**)&list, g_list);
    cudaGetSymbolAddress((void**)&slot, g_slot);

    reset_k<<<1, 32>>>(cnt);

    // h = LN(x) * ln1_w
    ln_k<<<Tt, 256>>>(x, ln1_w, nullptr, h, Dd, Dd, Dd);

    // cq = LN(h @ W_dq)
    launch_gemm<false, 0>(h, W_dq, nullptr, cq, Tt, QP, Dd, Dd, QP, QP,
                          nullptr, nullptr, nullptr, nullptr);
    ln_k<<<Tt, 256>>>(cq, q_ln_w, q_ln_b, cq, QP, QP, QP);

    // Q = cq @ W_uq
    launch_gemm<false, 0>(cq, W_uq, nullptr, Q, Tt, Dd, QP, QP, Dd, Dd,
                          nullptr, nullptr, nullptr, nullptr);

    // ckv = h @ W_dkv ; kvl = LN(ckv[:, :512])
    launch_gemm<false, 0>(h, W_dkv, nullptr, ckv, Tt, CKV, Dd, Dd, CKV, CKV,
                          nullptr, nullptr, nullptr, nullptr);
    ln_k<<<Tt, 256>>>(ckv, kv_ln_w, kv_ln_b, kvl, KVP, CKV, KVP);

    // KV = kvl @ W_ukv
    launch_gemm<false, 0>(kvl, W_ukv, nullptr, KV, Tt, UKVO, KVP, KVP, UKVO, UKVO,
                          nullptr, nullptr, nullptr, nullptr);

    // per-head q/k/v with RoPE
    {
        dim3 grid(Tt, Hh);
        build_qkv_k<<<grid, 64>>>(Q, KV, ckv, q, k, v);
    }

    // causal attention
    {
        dim3 grid(Ss / 128, Bb * Hh);
        attn_k<<<grid, 128>>>(q, k, v, o);
    }

    // x2 = x + o @ W_o^T
    launch_gemm<true, 1>(o, W_o, x, x2, Tt, Dd, Dd, Dd, Dd, Dd,
                         nullptr, nullptr, nullptr, nullptr);

    // out = x2 ; h2 = LN(x2) * ln2_w
    copy4_k<<<(Tt * Dd / 4 + 255) / 256, 256>>>(out, x2, Tt * Dd / 4);
    ln_k<<<Tt, 256>>>(x2, ln2_w, nullptr, h2, Dd, Dd, Dd);

    // shared experts (dense)
    for (int n = 0; n < NSs; n++) {
        launch_gemm<true, 2>(h2, s_fc + (size_t)n * FF * Dd, nullptr, ts,
                             Tt, FF, Dd, Dd, Dd, FF, nullptr, nullptr, nullptr, nullptr);
        launch_gemm<true, 4>(ts, s_proj + (size_t)n * Dd * FF, nullptr, out,
                             Tt, Dd, FF, FF, FF, Dd, nullptr, nullptr, nullptr, nullptr);
    }

    // routing
    route_k<<<Tt / 4, 128>>>(h2, cent, rbias, cnt, list, slot, gate);

    // routed experts: gathered fc (gelu) then gathered proj (gate-scaled)
    for (int e = 0; e < Ee; e++) {
        launch_gemm<true, 2>(h2, e_fc + (size_t)e * FF * Dd, nullptr, t1,
                             Tt, FF, Dd, Dd, Dd, FF,
                             list + e * Tt, slot + e * Tt, nullptr, cnt + e);
    }
    for (int e = 0; e < Ee; e++) {
        launch_gemm<true, 3>(t1, e_proj + (size_t)e * Dd * FF, nullptr, y,
                             Tt, Dd, FF, FF, FF, Dd,
                             slot + e * Tt, slot + e * Tt, gate + e * Tt, cnt + e);
    }

    // out += routed contributions
    addroute_k<<<(Tt * Dd + 255) / 256, 256>>>(out, y);
}

// round 5
// speedup vs baseline: 2.5305x; 2.5305x over previous
#include <cuda_runtime.h>
#include <math.h>

// ---------------- problem constants ----------------
constexpr int Bb = 4, Ss = 1024, Tt = Bb * Ss;   // 4096 tokens
constexpr int Dd = 768, Hh = 12, DH = 64, NOPE = 32, ROPE = 32;
constexpr int QP = 384, KVP = 512, CKV = 544;    // KVP + ROPE
constexpr int UKVO = Dd + Hh * NOPE;             // 1152
constexpr int Ee = 8, NSs = 2, FF = 3072;

// ---------------- scratch (device globals; no allocation) ----------------
__device__ float g_h   [(size_t)Tt * Dd];
__device__ float g_cq  [(size_t)Tt * QP];
__device__ float g_Q   [(size_t)Tt * Dd];
__device__ float g_ckv [(size_t)Tt * CKV];
__device__ float g_kvl [(size_t)Tt * KVP];
__device__ float g_KV  [(size_t)Tt * UKVO];
__device__ float g_q   [(size_t)Tt * Dd];   // [b][h][s][64]
__device__ float g_k   [(size_t)Tt * Dd];
__device__ float g_v   [(size_t)Tt * Dd];
__device__ float g_o   [(size_t)Tt * Dd];   // [t][h*64+d]
__device__ float g_x2  [(size_t)Tt * Dd];
__device__ float g_h2  [(size_t)Tt * Dd];
__device__ float g_ts  [(size_t)Tt * FF];        // shared-expert intermediate
__device__ float g_t1  [(size_t)2 * Tt * FF];    // routed fc output by slot
__device__ float g_y   [(size_t)2 * Tt * Dd];    // routed proj output by slot
__device__ int   g_cnt [Ee];
__device__ int   g_list[Ee * Tt];
__device__ int   g_slot[Ee * Tt];
__device__ float g_gate[Ee * Tt];

// ---------------- helpers ----------------
__device__ __forceinline__ float gelu_exact(float v) {
    return 0.5f * v * (1.0f + erff(v * 0.70710678118654752f));
}

__device__ __forceinline__ unsigned f2tf(float x) {
    unsigned u;
    asm("cvt.rna.tf32.f32 %0, %1;" : "=r"(u) : "f"(x));
    return u;
}

__device__ __forceinline__ void mma_tf32(float* c, const unsigned* a, const unsigned* b) {
    asm volatile(
        "mma.sync.aligned.m16n8k8.row.col.f32.tf32.tf32.f32 "
        "{%0,%1,%2,%3}, {%4,%5,%6,%7}, {%8,%9}, {%0,%1,%2,%3};"
        : "+f"(c[0]), "+f"(c[1]), "+f"(c[2]), "+f"(c[3])
        : "r"(a[0]), "r"(a[1]), "r"(a[2]), "r"(a[3]), "r"(b[0]), "r"(b[1]));
}

__device__ __forceinline__ void block_reduce2(float& s, float& s2) {
    __shared__ float sh[16], sh2[16];
    int lane = threadIdx.x & 31, w = threadIdx.x >> 5;
    #pragma unroll
    for (int o = 16; o; o >>= 1) {
        s  += __shfl_xor_sync(0xffffffffu, s,  o);
        s2 += __shfl_xor_sync(0xffffffffu, s2, o);
    }
    if (lane == 0) { sh[w] = s; sh2[w] = s2; }
    __syncthreads();
    int nw = blockDim.x >> 5;
    if (w == 0) {
        float a  = lane < nw ? sh[lane]  : 0.f;
        float a2 = lane < nw ? sh2[lane] : 0.f;
        #pragma unroll
        for (int o = 16; o; o >>= 1) {
            a  += __shfl_xor_sync(0xffffffffu, a,  o);
            a2 += __shfl_xor_sync(0xffffffffu, a2, o);
        }
        if (lane == 0) { sh[0] = a; sh2[0] = a2; }
    }
    __syncthreads();
    s = sh[0]; s2 = sh2[0];
}

// ---------------- layernorm: one block per row ----------------
__global__ void ln_k(const float* __restrict__ x, const float* __restrict__ w,
                     const float* __restrict__ b, float* __restrict__ y,
                     int len, int xs, int ys) {
    int row = blockIdx.x;
    const float* xp = x + (size_t)row * xs;
    float* yp = y + (size_t)row * ys;
    float s = 0.f, s2 = 0.f;
    for (int i = threadIdx.x; i < len; i += blockDim.x) {
        float v = xp[i]; s += v; s2 += v * v;
    }
    block_reduce2(s, s2);
    float mean = s / len;
    float var = fmaxf(s2 / len - mean * mean, 0.f);
    float inv = rsqrtf(var + 1e-5f);
    for (int i = threadIdx.x; i < len; i += blockDim.x) {
        float v = (xp[i] - mean) * inv * w[i];
        if (b) v += b[i];
        yp[i] = v;
    }
}

// ---------------- tf32 tensor-core tiled GEMM ----------------
// C[M,N] = A[M,K] * op(B); TB=false: B is [K,N]; TB=true: B is [N,K] (C = A B^T)
// EPI: 0 store, 1 +R, 2 gelu, 3 *rowscale, 4 accumulate into C
// Tile: BM=128, BN=64, BK=32. 256 threads = 8 warps (4x2), warp tile 32x32.
template<bool TB, int EPI>
__global__ __launch_bounds__(256, 3)
void gemm_tc(const float* __restrict__ A, const float* __restrict__ Bm,
             const float* __restrict__ R, float* __restrict__ C,
             int M, int N, int K, int lda, int ldb, int ldc,
             const int* __restrict__ gA, const int* __restrict__ gC,
             const float* __restrict__ gs, const int* __restrict__ dM) {
    int Me = dM ? *dM : M;
    int bm = blockIdx.y * 128, bn = blockIdx.x * 64;
    if (bm >= Me) return;

    __shared__ unsigned As[128][36];
    __shared__ unsigned Bs[64][36];

    int t = threadIdx.x;
    int lane = t & 31, wid = t >> 5;
    int wm = wid >> 1, wn = wid & 1;
    int g = lane >> 2, tg = lane & 3;

    float acc[2][4][4];
    #pragma unroll
    for (int i = 0; i < 2; i++)
        #pragma unroll
        for (int j = 0; j < 4; j++)
            #pragma unroll
            for (int l = 0; l < 4; l++) acc[i][j][l] = 0.f;

    // precompute A row gather for this thread's 4 load slots
    int a_ar[4], a_ac[4];
    const float* a_ptr[4];
    #pragma unroll
    for (int i = 0; i < 4; i++) {
        int idx = t + i * 256;
        a_ar[i] = idx >> 3;
        a_ac[i] = (idx & 7) * 4;
        int row = bm + a_ar[i];
        a_ptr[i] = nullptr;
        if (row < Me) {
            int aIdx = gA ? gA[row] : row;
            a_ptr[i] = A + (size_t)aIdx * lda;
        }
    }

    for (int k0 = 0; k0 < K; k0 += 32) {
        // ---- load A tile 128x32 (tf32-converted) ----
        #pragma unroll
        for (int i = 0; i < 4; i++) {
            uint4 u = {0u, 0u, 0u, 0u};
            if (a_ptr[i]) {
                float4 v = *(const float4*)(a_ptr[i] + k0 + a_ac[i]);
                u.x = f2tf(v.x); u.y = f2tf(v.y); u.z = f2tf(v.z); u.w = f2tf(v.w);
            }
            *(uint4*)&As[a_ar[i]][a_ac[i]] = u;
        }
        // ---- load B tile 64x32 ----
        if (TB) {
            #pragma unroll
            for (int i = 0; i < 2; i++) {
                int idx = t + i * 256;
                int br = idx >> 3, bc = (idx & 7) * 4;
                uint4 u = {0u, 0u, 0u, 0u};
                int col = bn + br;
                if (col < N) {
                    float4 v = *(const float4*)(Bm + (size_t)col * ldb + k0 + bc);
                    u.x = f2tf(v.x); u.y = f2tf(v.y); u.z = f2tf(v.z); u.w = f2tf(v.w);
                }
                *(uint4*)&Bs[br][bc] = u;
            }
        } else {
            #pragma unroll
            for (int i = 0; i < 2; i++) {
                int idx = t + i * 256;
                int kr = idx >> 4, c4 = (idx & 15) * 4;
                #pragma unroll
                for (int j = 0; j < 4; j++) {
                    int col = bn + c4 + j;
                    float v = (col < N) ? Bm[(size_t)(k0 + kr) * ldb + col] : 0.f;
                    Bs[c4 + j][kr] = f2tf(v);
                }
            }
        }
        __syncthreads();

        // ---- compute: 4 k-steps of m16n8k8 ----
        #pragma unroll
        for (int ks = 0; ks < 32; ks += 8) {
            unsigned af[2][4], bf[4][2];
            #pragma unroll
            for (int mt = 0; mt < 2; mt++) {
                int rb = wm * 32 + mt * 16;
                af[mt][0] = As[rb + g    ][ks + tg];
                af[mt][1] = As[rb + g + 8][ks + tg];
                af[mt][2] = As[rb + g    ][ks + tg + 4];
                af[mt][3] = As[rb + g + 8][ks + tg + 4];
            }
            #pragma unroll
            for (int nt = 0; nt < 4; nt++) {
                int nb = wn * 32 + nt * 8;
                bf[nt][0] = Bs[nb + g][ks + tg];
                bf[nt][1] = Bs[nb + g][ks + tg + 4];
            }
            #pragma unroll
            for (int mt = 0; mt < 2; mt++)
                #pragma unroll
                for (int nt = 0; nt < 4; nt++)
                    mma_tf32(acc[mt][nt], af[mt], bf[nt]);
        }
        __syncthreads();
    }

    // ---- epilogue ----
    #pragma unroll
    for (int mt = 0; mt < 2; mt++) {
        int r0 = bm + wm * 32 + mt * 16 + g;
        #pragma unroll
        for (int rr = 0; rr < 2; rr++) {
            int r = r0 + rr * 8;
            if (r >= Me) continue;
            int cr = gC ? gC[r] : r;
            float rs = (EPI == 3) ? gs[r] : 1.f;
            float* crow = C + (size_t)cr * ldc;
            const float* rrow = (EPI == 1) ? (R + (size_t)cr * ldc) : nullptr;
            #pragma unroll
            for (int nt = 0; nt < 4; nt++) {
                int col = bn + wn * 32 + nt * 8 + tg * 2;
                if (col >= N) continue;
                float v0 = acc[mt][nt][rr * 2 + 0];
                float v1 = acc[mt][nt][rr * 2 + 1];
                if (EPI == 1) { v0 += rrow[col]; v1 += rrow[col + 1]; }
                if (EPI == 2) { v0 = gelu_exact(v0); v1 = gelu_exact(v1); }
                if (EPI == 3) { v0 *= rs; v1 *= rs; }
                if (EPI == 4) {
                    crow[col]     += v0;
                    crow[col + 1] += v1;
                } else {
                    float2 w2 = make_float2(v0, v1);
                    *(float2*)&crow[col] = w2;
                }
            }
        }
    }
}

template<bool TB, int EPI>
static void launch_gemm(const float* A, const float* B, const float* R, float* C,
                        int M, int N, int K, int lda, int ldb, int ldc,
                        const int* gA, const int* gC, const float* gs, const int* dM) {
    dim3 grid((N + 63) / 64, (M + 127) / 128);
    gemm_tc<TB, EPI><<<grid, 256>>>(A, B, R, C, M, N, K, lda, ldb, ldc, gA, gC, gs, dM);
}

// ---------------- RoPE + per-head q/k/v layout ----------------
__global__ void build_qkv_k(const float* __restrict__ Q, const float* __restrict__ KV,
                            const float* __restrict__ ckv,
                            float* __restrict__ q, float* __restrict__ k,
                            float* __restrict__ v) {
    int t = blockIdx.x;
    int h = blockIdx.y;
    int d = threadIdx.x;          // 0..63
    int b = t / Ss, s = t - b * Ss;
    const float ln1e4_32 = 0.28782313662425574f;  // ln(10000)/32

    size_t dst = ((size_t)(b * Hh + h) * Ss + s) * 64 + d;

    float qv, kv;
    if (d < NOPE) {
        qv = Q [(size_t)t * Dd   + h * DH + d];
        kv = KV[(size_t)t * UKVO + h * (NOPE + DH) + d];
    } else {
        int j = d - NOPE;            // 0..31
        int j16 = j & 15;
        float freq = expf(-ln1e4_32 * (float)j16);
        float ang = (float)s * freq;
        float cs = cosf(ang), sn = sinf(ang);
        {
            float xv = Q[(size_t)t * Dd + h * DH + NOPE + j];
            float pr = (j < 16) ? Q[(size_t)t * Dd + h * DH + NOPE + j + 16]
                                : Q[(size_t)t * Dd + h * DH + NOPE + j - 16];
            qv = (j < 16) ? xv * cs - pr * sn : xv * cs + pr * sn;
        }
        {
            float xv = ckv[(size_t)t * CKV + KVP + j];
            float pr = (j < 16) ? ckv[(size_t)t * CKV + KVP + j + 16]
                                : ckv[(size_t)t * CKV + KVP + j - 16];
            kv = (j < 16) ? xv * cs - pr * sn : xv * cs + pr * sn;
        }
    }
    q[dst] = qv * 0.125f;   // 1/sqrt(64) folded into q
    k[dst] = kv;
    v[dst] = KV[(size_t)t * UKVO + h * (NOPE + DH) + NOPE + d];
}

// ---------------- causal flash attention: 1 thread = 1 query row ----------------
__global__ __launch_bounds__(128)
void attn_k(const float* __restrict__ q, const float* __restrict__ k,
            const float* __restrict__ v, float* __restrict__ o) {
    int bh = blockIdx.y;                // 0..B*H-1
    int qi = blockIdx.x * 128 + threadIdx.x;
    const float* qp = q + ((size_t)bh * Ss + qi) * 64;

    float qr[64];
    #pragma unroll
    for (int d = 0; d < 64; d++) qr[d] = qp[d];

    float acc[64];
    #pragma unroll
    for (int d = 0; d < 64; d++) acc[d] = 0.f;
    float m = -1e30f, l = 0.f;

    __shared__ float Ks[64][64];
    __shared__ float Vs[64][64];

    int ktmax = (blockIdx.x * 128 + 127) >> 6;
    for (int kt = 0; kt <= ktmax; kt++) {
        for (int i = threadIdx.x; i < 64 * 16; i += 128) {
            int row = i >> 4, c = i & 15;
            size_t base = ((size_t)bh * Ss + kt * 64 + row) * 64;
            ((float4*)&Ks[row][0])[c] = ((const float4*)(k + base))[c];
            ((float4*)&Vs[row][0])[c] = ((const float4*)(v + base))[c];
        }
        __syncthreads();
        int kbase = kt * 64;
        for (int kk = 0; kk < 64; kk++) {
            int key = kbase + kk;
            if (key > qi) break;
            float sc = 0.f;
            #pragma unroll
            for (int d = 0; d < 64; d++) sc += qr[d] * Ks[kk][d];
            float nm = fmaxf(m, sc);
            float corr = __expf(m - nm);
            float p = __expf(sc - nm);
            l = l * corr + p;
            #pragma unroll
            for (int d = 0; d < 64; d++) acc[d] = acc[d] * corr + p * Vs[kk][d];
            m = nm;
        }
        __syncthreads();
    }
    int b = bh / Hh, h = bh - b * Hh;
    float invl = 1.f / l;
    float* op = o + ((size_t)(b * Ss + qi)) * Dd + h * DH;
    #pragma unroll
    for (int d = 0; d < 64; d++) op[d] = acc[d] * invl;
}

// ---------------- MoE routing: one warp per token ----------------
__global__ void route_k(const float* __restrict__ h2, const float* __restrict__ cent,
                        const float* __restrict__ rb, int* __restrict__ cnt,
                        int* __restrict__ list, int* __restrict__ slot,
                        float* __restrict__ gate) {
    int gw = (blockIdx.x * blockDim.x + threadIdx.x) >> 5;
    int lane = threadIdx.x & 31;
    if (gw >= Tt) return;
    const float* hp = h2 + (size_t)gw * Dd;
    float raw[Ee];
    #pragma unroll
    for (int e = 0; e < Ee; e++) {
        float s = 0.f;
        const float* cp = cent + (size_t)e * Dd;
        for (int d = lane; d < Dd; d += 32) s += hp[d] * cp[d];
        #pragma unroll
        for (int o = 16; o; o >>= 1) s += __shfl_xor_sync(0xffffffffu, s, o);
        raw[e] = s;
    }
    if (lane == 0) {
        int e1 = 0; float b1 = -1e30f;
        #pragma unroll
        for (int e = 0; e < Ee; e++) {
            float bv = raw[e] + rb[e];
            if (bv > b1) { b1 = bv; e1 = e; }
        }
        int e2 = -1; float b2 = -1e30f;
        #pragma unroll
        for (int e = 0; e < Ee; e++) {
            if (e == e1) continue;
            float bv = raw[e] + rb[e];
            if (bv > b2) { b2 = bv; e2 = e; }
        }
        float w1 = 1.f / (1.f + expf(-raw[e1]));
        float w2 = 1.f / (1.f + expf(-raw[e2]));
        float inv = 1.f / (w1 + w2 + 1e-9f);
        w1 *= inv; w2 *= inv;
        int p1 = atomicAdd(&cnt[e1], 1);
        list[e1 * Tt + p1] = gw; slot[e1 * Tt + p1] = 2 * gw;     gate[e1 * Tt + p1] = w1;
        int p2 = atomicAdd(&cnt[e2], 1);
        list[e2 * Tt + p2] = gw; slot[e2 * Tt + p2] = 2 * gw + 1; gate[e2 * Tt + p2] = w2;
    }
}

// ---------------- small utility kernels ----------------
__global__ void reset_k(int* cnt) {
    if (threadIdx.x < Ee) cnt[threadIdx.x] = 0;
}
__global__ void copy4_k(float* __restrict__ dst, const float* __restrict__ src, int n4) {
    int i = blockIdx.x * blockDim.x + threadIdx.x;
    if (i < n4) ((float4*)dst)[i] = ((const float4*)src)[i];
}
__global__ void addroute_k(float* __restrict__ out, const float* __restrict__ y) {
    int i = blockIdx.x * blockDim.x + threadIdx.x;
    if (i < Tt * Dd) {
        int t = i / Dd, d = i - t * Dd;
        out[i] += y[(size_t)(2 * t) * Dd + d] + y[(size_t)(2 * t + 1) * Dd + d];
    }
}

// ---------------- launch sequence ----------------
extern "C" void kernel_launch(void* const* d_in, const int* in_sizes, int n_in,
                              void* d_out, int out_size) {
    const float* x        = (const float*)d_in[0];
    const float* ln1_w    = (const float*)d_in[1];
    const float* ln2_w    = (const float*)d_in[2];
    const float* W_dq     = (const float*)d_in[3];
    const float* W_uq     = (const float*)d_in[4];
    const float* q_ln_w   = (const float*)d_in[5];
    const float* q_ln_b   = (const float*)d_in[6];
    const float* W_dkv    = (const float*)d_in[7];
    const float* W_ukv    = (const float*)d_in[8];
    const float* kv_ln_w  = (const float*)d_in[9];
    const float* kv_ln_b  = (const float*)d_in[10];
    const float* W_o      = (const float*)d_in[11];
    const float* s_fc     = (const float*)d_in[12];
    const float* s_proj   = (const float*)d_in[13];
    const float* e_fc     = (const float*)d_in[14];
    const float* e_proj   = (const float*)d_in[15];
    const float* cent     = (const float*)d_in[16];
    const float* rbias    = (const float*)d_in[17];
    float* out = (float*)d_out;

    float *h, *cq, *Q, *ckv, *kvl, *KV, *q, *k, *v, *o, *x2, *h2, *ts, *t1, *y, *gate;
    int *cnt, *list, *slot;
    cudaGetSymbolAddress((void**)&h,    g_h);
    cudaGetSymbolAddress((void**)&cq,   g_cq);
    cudaGetSymbolAddress((void**)&Q,    g_Q);
    cudaGetSymbolAddress((void**)&ckv,  g_ckv);
    cudaGetSymbolAddress((void**)&kvl,  g_kvl);
    cudaGetSymbolAddress((void**)&KV,   g_KV);
    cudaGetSymbolAddress((void**)&q,    g_q);
    cudaGetSymbolAddress((void**)&k,    g_k);
    cudaGetSymbolAddress((void**)&v,    g_v);
    cudaGetSymbolAddress((void**)&o,    g_o);
    cudaGetSymbolAddress((void**)&x2,   g_x2);
    cudaGetSymbolAddress((void**)&h2,   g_h2);
    cudaGetSymbolAddress((void**)&ts,   g_ts);
    cudaGetSymbolAddress((void**)&t1,   g_t1);
    cudaGetSymbolAddress((void**)&y,    g_y);
    cudaGetSymbolAddress((void**)&gate, g_gate);
    cudaGetSymbolAddress((void**)&cnt,  g_cnt);
    cudaGetSymbolAddress((void**)&list, g_list);
    cudaGetSymbolAddress((void**)&slot, g_slot);

    reset_k<<<1, 32>>>(cnt);

    // h = LN(x) * ln1_w
    ln_k<<<Tt, 256>>>(x, ln1_w, nullptr, h, Dd, Dd, Dd);

    // cq = LN(h @ W_dq)
    launch_gemm<false, 0>(h, W_dq, nullptr, cq, Tt, QP, Dd, Dd, QP, QP,
                          nullptr, nullptr, nullptr, nullptr);
    ln_k<<<Tt, 256>>>(cq, q_ln_w, q_ln_b, cq, QP, QP, QP);

    // Q = cq @ W_uq
    launch_gemm<false, 0>(cq, W_uq, nullptr, Q, Tt, Dd, QP, QP, Dd, Dd,
                          nullptr, nullptr, nullptr, nullptr);

    // ckv = h @ W_dkv ; kvl = LN(ckv[:, :512])
    launch_gemm<false, 0>(h, W_dkv, nullptr, ckv, Tt, CKV, Dd, Dd, CKV, CKV,
                          nullptr, nullptr, nullptr, nullptr);
    ln_k<<<Tt, 256>>>(ckv, kv_ln_w, kv_ln_b, kvl, KVP, CKV, KVP);

    // KV = kvl @ W_ukv
    launch_gemm<false, 0>(kvl, W_ukv, nullptr, KV, Tt, UKVO, KVP, KVP, UKVO, UKVO,
                          nullptr, nullptr, nullptr, nullptr);

    // per-head q/k/v with RoPE
    {
        dim3 grid(Tt, Hh);
        build_qkv_k<<<grid, 64>>>(Q, KV, ckv, q, k, v);
    }

    // causal attention
    {
        dim3 grid(Ss / 128, Bb * Hh);
        attn_k<<<grid, 128>>>(q, k, v, o);
    }

    // x2 = x + o @ W_o^T
    launch_gemm<true, 1>(o, W_o, x, x2, Tt, Dd, Dd, Dd, Dd, Dd,
                         nullptr, nullptr, nullptr, nullptr);

    // out = x2 ; h2 = LN(x2) * ln2_w
    copy4_k<<<(Tt * Dd / 4 + 255) / 256, 256>>>(out, x2, Tt * Dd / 4);
    ln_k<<<Tt, 256>>>(x2, ln2_w, nullptr, h2, Dd, Dd, Dd);

    // shared experts (dense)
    for (int n = 0; n < NSs; n++) {
        launch_gemm<true, 2>(h2, s_fc + (size_t)n * FF * Dd, nullptr, ts,
                             Tt, FF, Dd, Dd, Dd, FF, nullptr, nullptr, nullptr, nullptr);
        launch_gemm<true, 4>(ts, s_proj + (size_t)n * Dd * FF, nullptr, out,
                             Tt, Dd, FF, FF, FF, Dd, nullptr, nullptr, nullptr, nullptr);
    }

    // routing
    route_k<<<Tt / 4, 128>>>(h2, cent, rbias, cnt, list, slot, gate);

    // routed experts: gathered fc (gelu) then gathered proj (gate-scaled)
    for (int e = 0; e < Ee; e++) {
        launch_gemm<true, 2>(h2, e_fc + (size_t)e * FF * Dd, nullptr, t1,
                             Tt, FF, Dd, Dd, Dd, FF,
                             list + e * Tt, slot + e * Tt, nullptr, cnt + e);
    }
    for (int e = 0; e < Ee; e++) {
        launch_gemm<true, 3>(t1, e_proj + (size_t)e * Dd * FF, nullptr, y,
                             Tt, Dd, FF, FF, FF, Dd,
                             slot + e * Tt, slot + e * Tt, gate + e * Tt, cnt + e);
    }

    // out += routed contributions
    addroute_k<<<(Tt * Dd + 255) / 256, 256>>>(out, y);
}